// round 7
// baseline (speedup 1.0000x reference)
#include <cuda_runtime.h>
#include <math.h>
#include <stdint.h>

#define BB   2
#define SS   2048
#define DMODEL 1024
#define HQ   16
#define HKV  4
#define DK   64
#define KVD  256   // HKV*DK

// ---------------- scratch (no allocations allowed) ----------------
__device__ float g_Q[BB*SS*DMODEL];
__device__ float g_K[BB*SS*KVD];
__device__ float g_V[BB*SS*KVD];
__device__ float g_attn[BB*SS*DMODEL];
__device__ float g_cos[SS*(DK/2)];
__device__ float g_sin[SS*(DK/2)];

// ---------------- helpers ----------------
__device__ __forceinline__ uint32_t f2tf(float x) {
    uint32_t r; asm("cvt.rna.tf32.f32 %0, %1;" : "=r"(r) : "f"(x)); return r;
}

__device__ __forceinline__ void mma_tf32(float* c, const uint32_t* a, const uint32_t* b) {
    asm volatile(
        "mma.sync.aligned.m16n8k8.row.col.f32.tf32.tf32.f32 "
        "{%0,%1,%2,%3}, {%4,%5,%6,%7}, {%8,%9}, {%0,%1,%2,%3};\n"
        : "+f"(c[0]), "+f"(c[1]), "+f"(c[2]), "+f"(c[3])
        : "r"(a[0]), "r"(a[1]), "r"(a[2]), "r"(a[3]), "r"(b[0]), "r"(b[1]));
}

__device__ __forceinline__ uint32_t smem_u32(const void* p) {
    uint32_t a;
    asm("{ .reg .u64 t; cvta.to.shared.u64 t, %1; cvt.u32.u64 %0, t; }" : "=r"(a) : "l"(p));
    return a;
}

__device__ __forceinline__ void cp16(uint32_t saddr, const void* g) {
    asm volatile("cp.async.cg.shared.global [%0], [%1], 16;" :: "r"(saddr), "l"(g));
}
#define CP_COMMIT() asm volatile("cp.async.commit_group;" ::: "memory")
#define CP_WAIT0()  asm volatile("cp.async.wait_group 0;" ::: "memory")

// ---------------- RoPE table ----------------
// theta_j = 1/(10000^(2j)/64); j>=5 -> inf -> theta=0 (fp32 overflow, matches ref)
__global__ void freq_rope_kernel(float* __restrict__ cosT, float* __restrict__ sinT) {
    int idx = blockIdx.x * blockDim.x + threadIdx.x;
    if (idx >= SS * (DK/2)) return;
    int s = idx / (DK/2);
    int j = idx % (DK/2);
    float p = powf(10000.0f, 2.0f * (float)j);
    float theta = 1.0f / (p / (float)DK);
    float ang = (float)s * theta;
    double a = (double)ang;
    cosT[idx] = (float)cos(a);
    sinT[idx] = (float)sin(a);
}

// ---------------- tf32 tensor-core GEMM body (R2-identical numerics) ---------
// C[M,N] = A[.]*W[.]^T + bias, optional fused RoPE in the epilogue.
#define GST 20

__device__ __forceinline__ void gemm_body(
        const float* __restrict__ A, const float* __restrict__ W,
        const float* __restrict__ bias, float* __restrict__ C,
        int N, int Kd, int rowbase, int colbase, int rope) {
    __shared__ uint32_t As[2][128*GST];
    __shared__ uint32_t Bs[2][128*GST];
    int tid = threadIdx.x;
    int lane = tid & 31, warp = tid >> 5;
    int wm = warp >> 2, wn = warp & 3;

    float acc[4][4][4];
#pragma unroll
    for (int a = 0; a < 4; a++)
#pragma unroll
        for (int b = 0; b < 4; b++)
#pragma unroll
            for (int c = 0; c < 4; c++) acc[a][b][c] = 0.0f;

    int lr = tid >> 2;
    int kc = (tid & 3) * 4;

    float4 pa[2], pw[2];
#pragma unroll
    for (int i = 0; i < 2; i++) {
        pa[i] = *(const float4*)&A[(size_t)(rowbase + lr + 64*i)*Kd + 0 + kc];
        pw[i] = *(const float4*)&W[(size_t)(colbase + lr + 64*i)*Kd + 0 + kc];
    }
#pragma unroll
    for (int i = 0; i < 2; i++) {
        uint4 ua = {f2tf(pa[i].x), f2tf(pa[i].y), f2tf(pa[i].z), f2tf(pa[i].w)};
        *(uint4*)&As[0][(lr + 64*i)*GST + kc] = ua;
        uint4 uw = {f2tf(pw[i].x), f2tf(pw[i].y), f2tf(pw[i].z), f2tf(pw[i].w)};
        *(uint4*)&Bs[0][(lr + 64*i)*GST + kc] = uw;
    }
    __syncthreads();

    int nk = Kd / 16;
    for (int t = 0; t < nk; t++) {
        int s = t & 1;
        if (t + 1 < nk) {
            int kb = (t+1)*16;
#pragma unroll
            for (int i = 0; i < 2; i++) {
                pa[i] = *(const float4*)&A[(size_t)(rowbase + lr + 64*i)*Kd + kb + kc];
                pw[i] = *(const float4*)&W[(size_t)(colbase + lr + 64*i)*Kd + kb + kc];
            }
        }
#pragma unroll
        for (int ks = 0; ks < 2; ks++) {
            int k0 = ks * 8;
            uint32_t af[4][4], bf[4][2];
#pragma unroll
            for (int mi = 0; mi < 4; mi++) {
                int row = wm*64 + mi*16 + (lane >> 2);
                const uint32_t* p = &As[s][row*GST + k0 + (lane & 3)];
                af[mi][0] = p[0];
                af[mi][1] = p[8*GST];
                af[mi][2] = p[4];
                af[mi][3] = p[8*GST + 4];
            }
#pragma unroll
            for (int ni = 0; ni < 4; ni++) {
                int col = wn*32 + ni*8 + (lane >> 2);
                const uint32_t* p = &Bs[s][col*GST + k0 + (lane & 3)];
                bf[ni][0] = p[0];
                bf[ni][1] = p[4];
            }
#pragma unroll
            for (int mi = 0; mi < 4; mi++)
#pragma unroll
                for (int ni = 0; ni < 4; ni++)
                    mma_tf32(acc[mi][ni], af[mi], bf[ni]);
        }
        if (t + 1 < nk) {
            int sn = (t+1) & 1;
#pragma unroll
            for (int i = 0; i < 2; i++) {
                uint4 ua = {f2tf(pa[i].x), f2tf(pa[i].y), f2tf(pa[i].z), f2tf(pa[i].w)};
                *(uint4*)&As[sn][(lr + 64*i)*GST + kc] = ua;
                uint4 uw = {f2tf(pw[i].x), f2tf(pw[i].y), f2tf(pw[i].z), f2tf(pw[i].w)};
                *(uint4*)&Bs[sn][(lr + 64*i)*GST + kc] = uw;
            }
        }
        __syncthreads();
    }

#pragma unroll
    for (int mi = 0; mi < 4; mi++) {
        int row = rowbase + wm*64 + mi*16 + (lane >> 2);
#pragma unroll
        for (int ni = 0; ni < 4; ni++) {
            int col = colbase + wn*32 + ni*8 + 2*(lane & 3);
            float c0 = bias[col], c1 = bias[col+1];
            float2 v0 = {acc[mi][ni][0] + c0, acc[mi][ni][1] + c1};
            float2 v1 = {acc[mi][ni][2] + c0, acc[mi][ni][3] + c1};
            if (rope) {
                int s0 = row & (SS - 1);
                int pr = (col & 63) >> 1;
                float cc = g_cos[s0*32 + pr], sn = g_sin[s0*32 + pr];
                float x1 = v0.x, x2 = v0.y;
                v0.x = x1*cc - x2*sn;
                v0.y = x2*sn + x1*cc;
                float c8 = g_cos[(s0+8)*32 + pr], s8 = g_sin[(s0+8)*32 + pr];
                float y1 = v1.x, y2 = v1.y;
                v1.x = y1*c8 - y2*s8;
                v1.y = y2*s8 + y1*c8;
            }
            *(float2*)&C[(size_t)row*N + col] = v0;
            *(float2*)&C[(size_t)(row+8)*N + col] = v1;
        }
    }
}

// Fused Q+K+V projection (384 CTAs) with RoPE folded into Q/K epilogues.
__global__ void __launch_bounds__(256) gemm_qkv(
        const float* __restrict__ x,
        const float* __restrict__ wq, const float* __restrict__ bq,
        const float* __restrict__ wk, const float* __restrict__ bk,
        const float* __restrict__ wv, const float* __restrict__ bv) {
    int id = blockIdx.x;
    const float* W; const float* bias; float* C;
    int N, rowbase, colbase, rope;
    if (id < 256) {
        W = wq; bias = bq; C = g_Q; N = DMODEL;
        rowbase = (id >> 3) * 128; colbase = (id & 7) * 128; rope = 1;
    } else if (id < 320) {
        int i = id - 256;
        W = wk; bias = bk; C = g_K; N = KVD;
        rowbase = (i >> 1) * 128; colbase = (i & 1) * 128; rope = 1;
    } else {
        int i = id - 320;
        W = wv; bias = bv; C = g_V; N = KVD;
        rowbase = (i >> 1) * 128; colbase = (i & 1) * 128; rope = 0;
    }
    gemm_body(x, W, bias, C, N, DMODEL, rowbase, colbase, rope);
}

// Output projection.
__global__ void __launch_bounds__(256) gemm_o(
        const float* __restrict__ A, const float* __restrict__ W,
        const float* __restrict__ bias, float* __restrict__ C) {
    gemm_body(A, W, bias, C, DMODEL, DMODEL, blockIdx.y*128, blockIdx.x*128, 0);
}

// ---------------- flash attention, tf32 mma.sync, GQA-fused -------------------
// CTA: 256 thr = 2 q-heads x 4 row-subtiles, 64 q-rows, shared K/V.
// Stage layout (per stage, 8960 words):
//   Kp [64 keys][72]  pair-interleaved: word key*72 + kk*8 + 2q = K[key][kk*8+q],
//                     next word = K[key][kk*8+q+4]   -> B-frag = 1 LDS.64
//   Vp [32 slots][136] slot = kk*4+q: word slot*136 + d*2 = V[kk*8+q][d],
//                     next word = V[kk*8+q+4][d]     -> B-frag = 1 LDS.64
// P for PV is staged in the *other* (dead) stage: g=0 -> K region, g=1 -> V region.
// RAW is written by cp.async in EXACTLY the per-task order fill_stage reads it,
// so every RAW byte is same-thread (cp.async.wait_group visibility is per-thread).
#define KP_ST 72
#define VP_ST 136
#define STAGE_W (64*KP_ST + 32*VP_ST)      // 8960 words
#define ATT_SMEM (2*STAGE_W*4 + 8192*4)    // 104448 bytes
#define P_ST 68

// cp.async issue: task-ordered, same-thread as fill_stage consumption.
__device__ __forceinline__ void issue_tile(uint32_t rawK, uint32_t rawV,
                                           const float* Kb, const float* Vb,
                                           int k0, int tid) {
#pragma unroll
    for (int i = 0; i < 2; i++) {
        int task = tid + 256*i;
        int row = task >> 3, j = task & 7;
        const float* g = &Kb[(size_t)(k0 + row)*KVD + j*8];
        cp16(rawK + task*32,      g);
        cp16(rawK + task*32 + 16, g + 4);
    }
#pragma unroll
    for (int i = 0; i < 2; i++) {
        int task = tid + 256*i;
        int slot = task >> 4, seg = task & 15;
        int k = (slot >> 2)*8 + (slot & 3);
        cp16(rawV + task*32,      &Vb[(size_t)(k0 + k)*KVD + seg*4]);
        cp16(rawV + task*32 + 16, &Vb[(size_t)(k0 + k + 4)*KVD + seg*4]);
    }
    CP_COMMIT();
}

__device__ __forceinline__ void fill_stage(uint32_t* Kp, uint32_t* Vp,
                                           const float* RAW, int tid) {
    // K: 512 tasks (row 0..63, j 0..7), words task*8 .. +7 (same-thread)
#pragma unroll
    for (int i = 0; i < 2; i++) {
        int task = tid + 256*i;
        int row = task >> 3, j = task & 7;
        float4 a = *(const float4*)(RAW + task*8);
        float4 b = *(const float4*)(RAW + task*8 + 4);
        uint4 w0 = {f2tf(a.x), f2tf(b.x), f2tf(a.y), f2tf(b.y)};
        uint4 w1 = {f2tf(a.z), f2tf(b.z), f2tf(a.w), f2tf(b.w)};
        *(uint4*)&Kp[row*KP_ST + j*8]     = w0;
        *(uint4*)&Kp[row*KP_ST + j*8 + 4] = w1;
    }
    // V: 512 tasks (slot 0..31, seg 0..15), words 4096 + task*8 .. +7
    const float* RV = RAW + 4096;
#pragma unroll
    for (int i = 0; i < 2; i++) {
        int task = tid + 256*i;
        int slot = task >> 4, seg = task & 15;
        float4 a = *(const float4*)(RV + task*8);       // V[k][seg*4..+3]
        float4 b = *(const float4*)(RV + task*8 + 4);   // V[k+4][seg*4..+3]
        uint4 w0 = {f2tf(a.x), f2tf(b.x), f2tf(a.y), f2tf(b.y)};
        uint4 w1 = {f2tf(a.z), f2tf(b.z), f2tf(a.w), f2tf(b.w)};
        *(uint4*)&Vp[slot*VP_ST + seg*8]     = w0;
        *(uint4*)&Vp[slot*VP_ST + seg*8 + 4] = w1;
    }
}

__global__ void __launch_bounds__(256, 2) attn_tf32() {
    extern __shared__ uint32_t smA[];
    uint32_t* TF  = smA;                       // 2 tf32 stages
    float*    RAW = (float*)(smA + 2*STAGE_W); // K raw [0,4096), V raw [4096,8192)
    uint32_t rawK = smem_u32(RAW);
    uint32_t rawV = rawK + 4096*4;

    int tid = threadIdx.x, lane = tid & 31, warp = tid >> 5;
    int g = warp >> 2, sub = warp & 3;
    int qt = (int)gridDim.x - 1 - (int)blockIdx.x;
    int y = blockIdx.y;
    int b = y >> 3, kvh = (y >> 1) & 3, hg = y & 1;
    int h = kvh*4 + hg*2 + g;

    const float* Qb = g_Q + (size_t)b*SS*DMODEL + h*DK;
    const float* Kb = g_K + (size_t)b*SS*KVD + kvh*DK;
    const float* Vb = g_V + (size_t)b*SS*KVD + kvh*DK;
    int q0 = qt * 64;
    int r1 = lane >> 2;
    int q  = lane & 3;
    int qrow = 16*sub + r1;

    // Q fragments, pre-scaled by 1/sqrt(64)
    uint32_t qf[8][4];
#pragma unroll
    for (int kk = 0; kk < 8; kk++) {
        int d = kk*8 + q;
        const float* p = &Qb[(size_t)(q0 + qrow)*DMODEL + d];
        qf[kk][0] = f2tf(p[0] * 0.125f);
        qf[kk][1] = f2tf(p[(size_t)8*DMODEL] * 0.125f);
        qf[kk][2] = f2tf(p[4] * 0.125f);
        qf[kk][3] = f2tf(p[(size_t)8*DMODEL + 4] * 0.125f);
    }

    float m1 = -1e30f, m2 = -1e30f, l1 = 0.0f, l2 = 0.0f;
    float of[8][4];
#pragma unroll
    for (int n = 0; n < 8; n++)
#pragma unroll
        for (int j = 0; j < 4; j++) of[n][j] = 0.0f;

    // prefetch tile 0 into RAW, convert into stage 0 (same-thread bytes)
    issue_tile(rawK, rawV, Kb, Vb, 0, tid);
    CP_WAIT0();
    fill_stage(TF, TF + 64*KP_ST, RAW, tid);
    __syncthreads();

    for (int kt = 0; kt <= qt; kt++) {
        int s = kt & 1;
        const uint32_t* Kp = TF + s*STAGE_W;
        const uint32_t* Vp = Kp + 64*KP_ST;
        uint32_t* stageN = TF + (s^1)*STAGE_W;
        uint32_t* Pb = stageN + (g ? 64*KP_ST : 0);   // dead region this step

        // issue cp.async for next tile
        if (kt < qt) issue_tile(rawK, rawV, Kb, Vb, (kt+1)*64, tid);

        // S = (Q/8) K^T
        float sf[8][4];
#pragma unroll
        for (int n = 0; n < 8; n++)
#pragma unroll
            for (int j = 0; j < 4; j++) sf[n][j] = 0.0f;
#pragma unroll
        for (int n = 0; n < 8; n++) {
            int key = n*8 + r1;
#pragma unroll
            for (int kk = 0; kk < 8; kk++) {
                uint2 b2 = *(const uint2*)&Kp[key*KP_ST + kk*8 + 2*q];
                uint32_t bfr[2] = {b2.x, b2.y};
                mma_tf32(sf[n], qf[kk], bfr);
            }
        }

        // causal mask on diagonal tile
        if (kt == qt) {
#pragma unroll
            for (int n = 0; n < 8; n++) {
                int col = n*8 + 2*q;
                if (col     > qrow)     sf[n][0] = -1e30f;
                if (col + 1 > qrow)     sf[n][1] = -1e30f;
                if (col     > qrow + 8) sf[n][2] = -1e30f;
                if (col + 1 > qrow + 8) sf[n][3] = -1e30f;
            }
        }

        // online softmax
        float mx1 = -1e30f, mx2 = -1e30f;
#pragma unroll
        for (int n = 0; n < 8; n++) {
            mx1 = fmaxf(mx1, fmaxf(sf[n][0], sf[n][1]));
            mx2 = fmaxf(mx2, fmaxf(sf[n][2], sf[n][3]));
        }
        mx1 = fmaxf(mx1, __shfl_xor_sync(0xffffffffu, mx1, 1));
        mx1 = fmaxf(mx1, __shfl_xor_sync(0xffffffffu, mx1, 2));
        mx2 = fmaxf(mx2, __shfl_xor_sync(0xffffffffu, mx2, 1));
        mx2 = fmaxf(mx2, __shfl_xor_sync(0xffffffffu, mx2, 2));
        float mn1 = fmaxf(m1, mx1), mn2 = fmaxf(m2, mx2);
        float c1 = __expf(m1 - mn1), c2 = __expf(m2 - mn2);
        float s1 = 0.0f, s2 = 0.0f;
#pragma unroll
        for (int n = 0; n < 8; n++) {
            sf[n][0] = __expf(sf[n][0] - mn1);
            sf[n][1] = __expf(sf[n][1] - mn1);
            sf[n][2] = __expf(sf[n][2] - mn2);
            sf[n][3] = __expf(sf[n][3] - mn2);
            s1 += sf[n][0] + sf[n][1];
            s2 += sf[n][2] + sf[n][3];
        }
        s1 += __shfl_xor_sync(0xffffffffu, s1, 1);
        s1 += __shfl_xor_sync(0xffffffffu, s1, 2);
        s2 += __shfl_xor_sync(0xffffffffu, s2, 1);
        s2 += __shfl_xor_sync(0xffffffffu, s2, 2);
        l1 = l1*c1 + s1;  l2 = l2*c2 + s2;
        m1 = mn1;         m2 = mn2;
#pragma unroll
        for (int n = 0; n < 8; n++) {
            of[n][0] *= c1; of[n][1] *= c1;
            of[n][2] *= c2; of[n][3] *= c2;
        }

        // P (tf32, same cvt point as before) into warp-private smem rows
#pragma unroll
        for (int n = 0; n < 8; n++) {
            uint2 w0 = {f2tf(sf[n][0]), f2tf(sf[n][1])};
            *(uint2*)&Pb[qrow*P_ST + n*8 + 2*q] = w0;
            uint2 w1 = {f2tf(sf[n][2]), f2tf(sf[n][3])};
            *(uint2*)&Pb[(qrow+8)*P_ST + n*8 + 2*q] = w1;
        }
        __syncwarp();

        // O += P V
#pragma unroll
        for (int kk = 0; kk < 8; kk++) {
            uint32_t pa[4];
            pa[0] = Pb[qrow*P_ST + kk*8 + q];
            pa[1] = Pb[(qrow+8)*P_ST + kk*8 + q];
            pa[2] = Pb[qrow*P_ST + kk*8 + q + 4];
            pa[3] = Pb[(qrow+8)*P_ST + kk*8 + q + 4];
            int slot = kk*4 + q;
#pragma unroll
            for (int n = 0; n < 8; n++) {
                uint2 v2 = *(const uint2*)&Vp[slot*VP_ST + (n*8 + r1)*2];
                uint32_t vb[2] = {v2.x, v2.y};
                mma_tf32(of[n], pa, vb);
            }
        }

        __syncthreads();   // all warps done with P (in stageN) before cvt overwrites it
        if (kt < qt) {
            CP_WAIT0();                                   // own copies landed
            fill_stage(stageN, stageN + 64*KP_ST, RAW, tid);  // same-thread bytes
        }
        __syncthreads();   // stage ready; RAW reusable
    }

    float inv1 = 1.0f / l1, inv2 = 1.0f / l2;
    float* Ob = g_attn + (size_t)b*SS*DMODEL + h*DK;
#pragma unroll
    for (int n = 0; n < 8; n++) {
        int col = n*8 + 2*q;
        float2 v0 = {of[n][0]*inv1, of[n][1]*inv1};
        *(float2*)&Ob[(size_t)(q0 + qrow)*DMODEL + col] = v0;
        float2 v1 = {of[n][2]*inv2, of[n][3]*inv2};
        *(float2*)&Ob[(size_t)(q0 + qrow + 8)*DMODEL + col] = v1;
    }
}

// ---------------- launch ----------------
extern "C" void kernel_launch(void* const* d_in, const int* in_sizes, int n_in,
                              void* d_out, int out_size) {
    const float* x  = (const float*)d_in[0];
    const float* wq = (const float*)d_in[1];
    const float* bq = (const float*)d_in[2];
    const float* wk = (const float*)d_in[3];
    const float* bk = (const float*)d_in[4];
    const float* wv = (const float*)d_in[5];
    const float* bv = (const float*)d_in[6];
    const float* wo = (const float*)d_in[7];
    const float* bo = (const float*)d_in[8];
    float* out = (float*)d_out;

    float *A, *cT, *sT;
    cudaGetSymbolAddress((void**)&A,  g_attn);
    cudaGetSymbolAddress((void**)&cT, g_cos);
    cudaGetSymbolAddress((void**)&sT, g_sin);

    static int cfg_done = 0;
    if (!cfg_done) {
        cudaFuncSetAttribute(attn_tf32, cudaFuncAttributeMaxDynamicSharedMemorySize, ATT_SMEM);
        cfg_done = 1;
    }

    // RoPE tables first (QKV epilogues consume them)
    freq_rope_kernel<<<(SS*(DK/2) + 255)/256, 256>>>(cT, sT);

    // fused Q+K+V projections with RoPE in the epilogue
    gemm_qkv<<<384, 256>>>(x, wq, bq, wk, bk, wv, bv);

    // attention (2 heads per CTA share K/V)
    attn_tf32<<<dim3(SS/64, BB*HKV*2), 256, ATT_SMEM>>>();

    // output projection
    gemm_o<<<dim3(DMODEL/128, BB*SS/128), 256>>>(A, wo, bo, out);
}